// round 3
// baseline (speedup 1.0000x reference)
#include <cuda_runtime.h>
#include <math.h>
#include <stdint.h>

// Problem constants (fixed by the reference: T=1024, B=32, I=H=512)
#define T_STEPS 1024
#define BATCH   32
#define HID     512
#define INP     512
#define G4      2048        // 4*HID
#define NCTA    128         // persistent CTAs (1/SM, all resident in wave 1)
#define TPB     256

// Output layout: (output[T,B,H], h_T[1,B,H], c_T[1,B,H], all_hidden[T,B,H])
#define OFF_HT  ((size_t)T_STEPS * BATCH * HID)
#define OFF_CT  (OFF_HT + (size_t)BATCH * HID)
#define OFF_ALL (OFF_CT + (size_t)BATCH * HID)

// Scratch: precomputed x@Wx^T + b for all timesteps (256 MB, static device mem)
__device__ float g_xp[(size_t)T_STEPS * BATCH * G4];
// 2-deep ring of hidden-state broadcast buffers
__device__ float g_h[2][BATCH * HID];
// Per-CTA publish flags: g_flag[j] = number of h versions CTA j has published.
// Reset to 0 at the end of every launch (behind the end barrier) -> replay-safe.
__device__ int g_flag[NCTA];
// End-of-kernel barrier state (sense-reversing, replay-consistent)
__device__ unsigned g_count = 0;
__device__ volatile unsigned g_sense = 0;

// ---------------------------------------------------------------------------
// Phase 1: XP[m][n] = X[m][:] . Wx[n][:] + bias[n],  M=32768, N=2048, K=512
// (unchanged from the passing R2 kernel: 64x128 tile, prefetched)
// ---------------------------------------------------------------------------
__global__ void __launch_bounds__(256, 2) pregemm_kernel(
    const float* __restrict__ X,
    const float* __restrict__ Wx,
    const float* __restrict__ bias)
{
    __shared__ float As[16][68];
    __shared__ float Bs[16][132];

    const int t  = threadIdx.x;
    const int m0 = blockIdx.y * 64;
    const int n0 = blockIdx.x * 128;
    const int tm = (t >> 4) << 2;
    const int tn = (t & 15) << 3;
    const int lr = t >> 2;
    const int lk = (t & 3) << 2;

    float acc[4][8];
#pragma unroll
    for (int i = 0; i < 4; i++)
#pragma unroll
        for (int j = 0; j < 8; j++) acc[i][j] = 0.f;

    const float* Arow  = X  + (size_t)(m0 + lr) * INP + lk;
    const float* Brow0 = Wx + (size_t)(n0 + lr) * INP + lk;
    const float* Brow1 = Wx + (size_t)(n0 + 64 + lr) * INP + lk;

    float4 av = *(const float4*)(Arow);
    float4 b0 = *(const float4*)(Brow0);
    float4 b1 = *(const float4*)(Brow1);

    for (int kt = 0; kt < INP; kt += 16) {
        __syncthreads();
        As[lk + 0][lr] = av.x; As[lk + 1][lr] = av.y;
        As[lk + 2][lr] = av.z; As[lk + 3][lr] = av.w;
        Bs[lk + 0][lr] = b0.x; Bs[lk + 1][lr] = b0.y;
        Bs[lk + 2][lr] = b0.z; Bs[lk + 3][lr] = b0.w;
        Bs[lk + 0][64 + lr] = b1.x; Bs[lk + 1][64 + lr] = b1.y;
        Bs[lk + 2][64 + lr] = b1.z; Bs[lk + 3][64 + lr] = b1.w;
        __syncthreads();

        if (kt + 16 < INP) {
            av = *(const float4*)(Arow  + kt + 16);
            b0 = *(const float4*)(Brow0 + kt + 16);
            b1 = *(const float4*)(Brow1 + kt + 16);
        }

#pragma unroll
        for (int k = 0; k < 16; k++) {
            float4 a = *(const float4*)&As[k][tm];
            float4 p = *(const float4*)&Bs[k][tn];
            float4 q = *(const float4*)&Bs[k][tn + 4];
            float ar[4] = {a.x, a.y, a.z, a.w};
            float br[8] = {p.x, p.y, p.z, p.w, q.x, q.y, q.z, q.w};
#pragma unroll
            for (int i = 0; i < 4; i++)
#pragma unroll
                for (int j = 0; j < 8; j++) acc[i][j] += ar[i] * br[j];
        }
    }

    float bl[8];
#pragma unroll
    for (int j = 0; j < 8; j++) bl[j] = bias[n0 + tn + j];
#pragma unroll
    for (int i = 0; i < 4; i++) {
        float4 s0 = make_float4(acc[i][0] + bl[0], acc[i][1] + bl[1],
                                acc[i][2] + bl[2], acc[i][3] + bl[3]);
        float4 s1 = make_float4(acc[i][4] + bl[4], acc[i][5] + bl[5],
                                acc[i][6] + bl[6], acc[i][7] + bl[7]);
        float* dst = g_xp + (size_t)(m0 + tm + i) * G4 + n0 + tn;
        *(float4*)dst       = s0;
        *(float4*)(dst + 4) = s1;
    }
}

// ---------------------------------------------------------------------------
// Phase 2 helpers
// ---------------------------------------------------------------------------
__device__ __forceinline__ float sigmoidf_(float x) {
    return 1.f / (1.f + expf(-x));
}

// Packed fp32x2 FMA (Blackwell): d = a*b + c elementwise on two packed floats.
__device__ __forceinline__ unsigned long long ffma2(
    unsigned long long a, unsigned long long b, unsigned long long c)
{
    unsigned long long d;
    asm("fma.rn.f32x2 %0, %1, %2, %3;" : "=l"(d) : "l"(a), "l"(b), "l"(c));
    return d;
}

__device__ __forceinline__ float hadd2(unsigned long long v) {
    float lo, hi;
    asm("mov.b64 {%0,%1}, %2;" : "=f"(lo), "=f"(hi) : "l"(v));
    return lo + hi;
}

#define NAMED_BAR(id, cnt) \
    asm volatile("bar.sync %0, %1;" :: "r"(id), "r"(cnt) : "memory")

// Poll all 128 flags until min >= target. Warp-collective (all 32 lanes).
__device__ __forceinline__ void wait_flags(int target, int lane) {
    const int4* fp = ((const int4*)g_flag) + lane;   // 32 lanes x int4 = 128
    for (;;) {
        int4 v;
        asm volatile("ld.global.cg.v4.b32 {%0,%1,%2,%3}, [%4];"
                     : "=r"(v.x), "=r"(v.y), "=r"(v.z), "=r"(v.w)
                     : "l"(fp) : "memory");
        int m = min(min(v.x, v.y), min(v.z, v.w));
        if (__all_sync(0xffffffffu, m >= target)) break;
        __nanosleep(32);
    }
}

__device__ __forceinline__ void end_barrier(unsigned lsense) {
    __syncthreads();
    if (threadIdx.x == 0) {
        __threadfence();
        unsigned s = lsense ^ 1u;
        if (atomicAdd(&g_count, 1u) == (unsigned)(gridDim.x - 1)) {
            atomicExch(&g_count, 0u);
            __threadfence();
            g_sense = s;
        } else {
            while (g_sense != s) __nanosleep(64);
        }
        __threadfence();
    }
    __syncthreads();
}

// SMEM layout (floats): hs[32][516] | ws[16][512] | part[128][20]
#define HS_STR4   129                              // float4 stride per batch row
#define SM_HS     0
#define SM_WS     (32 * 516)                       // 16512
#define SM_PART   (SM_WS + 16 * 512)               // 24704
#define PART_STR  20
#define SM_TOTALF (SM_PART + 128 * PART_STR)       // 27264
#define SMEM_BYTES (SM_TOTALF * 4)                 // 109056 B

// ---------------------------------------------------------------------------
// Phase 2: persistent recurrent kernel. 128 CTAs x 256 threads, 1 CTA/SM.
// CTA owns 4 hidden units (16 gate cols of Wh, SMEM-resident, fp32x2 FMA).
// Warp w: k-quarter kq=w>>1, col-group cg=w&1 (8 cols). Lane = batch.
// Sync = per-CTA publish flags (no atomic barrier in the step loop).
// ---------------------------------------------------------------------------
__global__ void __launch_bounds__(256, 1) lstm_kernel(
    const float* __restrict__ Wh,
    const float* __restrict__ h0,
    const float* __restrict__ c0,
    float* __restrict__ out)
{
    extern __shared__ __align__(16) float sm[];
    float* hs   = sm + SM_HS;
    float* ws   = sm + SM_WS;
    float* part = sm + SM_PART;
    float4* hs4 = (float4*)hs;

    const int t    = threadIdx.x;
    const int lane = t & 31;
    const int wid  = t >> 5;
    const int kq   = wid >> 1;          // k-quarter 0..3
    const int cg   = wid & 1;           // col-group 0..1 (8 cols each)
    const int u0   = blockIdx.x * 4;

    const unsigned lsense = g_sense;    // stable snapshot (no writers until end)

    // Load this CTA's 16 Wh columns into SMEM: ws[col][k], col = unit*4 + gate.
#pragma unroll
    for (int i = 0; i < 8; i++) {
        int j  = t + i * 256;           // 0..2047 float4s
        int lc = j >> 7;                // col 0..15
        int kf = j & 127;
        int ul = lc >> 2, q = lc & 3;
        float4 v = *(const float4*)(Wh + (size_t)(q * HID + u0 + ul) * HID + kf * 4);
        *(float4*)(ws + lc * 512 + kf * 4) = v;
    }

    // Elementwise mapping (t < 128): eb = batch, eu = local unit
    const int eb = t >> 2;
    const int eu = t & 3;
    float cc = 0.f, hh = 0.f;
    if (t < 128) {
        cc = c0[eb * HID + u0 + eu];
        hh = h0[eb * HID + u0 + eu];
        g_h[0][eb * HID + u0 + eu] = hh;    // publish h^0 chunk
    }
    __syncthreads();
    if (t == 0) {
        __threadfence();
        __stcg(&g_flag[blockIdx.x], 1);     // h^0 available
    }

    // Pointers for compute phase
    const float4* wbase = ((const float4*)ws) + (cg * 8) * 128 + kq * 32;

    for (int ts = 0; ts < T_STEPS; ts++) {
        // One sync point: wait until every CTA published h^ts.
        wait_flags(ts + 1, lane);

        // x-part prefetch for the elementwise phase (overlaps everything below)
        float xq0 = 0.f, xq1 = 0.f, xq2 = 0.f, xq3 = 0.f;
        if (t < 128) {
            const float* xp = g_xp + ((size_t)ts * BATCH + eb) * G4 + (u0 + eu);
            xq0 = __ldg(xp);
            xq1 = __ldg(xp + 512);
            xq2 = __ldg(xp + 1024);
            xq3 = __ldg(xp + 1536);
        }

        // Load my half of k-quarter kq of h (L2-coherent) into padded SMEM.
        const float4* hsrc4 = (const float4*)g_h[ts & 1];
#pragma unroll
        for (int it = 0; it < 16; it++) {
            int j  = lane + it * 32 + cg * 512;   // 0..1023 within quarter
            int b  = j >> 5;                      // batch
            int f4 = j & 31;                      // float4 within quarter
            float4 v = __ldcg(hsrc4 + b * 128 + kq * 32 + f4);
            hs4[b * HS_STR4 + kq * 32 + f4] = v;
        }
        NAMED_BAR(1 + kq, 64);                    // sync with quarter partner

        // 8 gate-col dot products over this warp's k-quarter (128 elements)
        unsigned long long acc[8];
#pragma unroll
        for (int j = 0; j < 8; j++) acc[j] = 0ull;

        const float4* hp = hs4 + lane * HS_STR4 + kq * 32;
#pragma unroll 4
        for (int ki = 0; ki < 32; ki++) {
            ulonglong2 hv = *(const ulonglong2*)(hp + ki);
#pragma unroll
            for (int j = 0; j < 8; j++) {
                ulonglong2 wv = *(const ulonglong2*)(wbase + j * 128 + ki);
                acc[j] = ffma2(hv.x, wv.x, acc[j]);
                acc[j] = ffma2(hv.y, wv.y, acc[j]);
            }
        }

        {
            float a0 = hadd2(acc[0]), a1 = hadd2(acc[1]);
            float a2 = hadd2(acc[2]), a3 = hadd2(acc[3]);
            float a4 = hadd2(acc[4]), a5 = hadd2(acc[5]);
            float a6 = hadd2(acc[6]), a7 = hadd2(acc[7]);
            float* pp = part + (kq * 32 + lane) * PART_STR + cg * 8;
            *(float4*)pp       = make_float4(a0, a1, a2, a3);
            *(float4*)(pp + 4) = make_float4(a4, a5, a6, a7);
        }
        __syncthreads();                          // partials visible to all

        if (t < 128) {
            float pi = xq0, pf = xq1, pg = xq2, po = xq3;
#pragma unroll
            for (int q4 = 0; q4 < 4; q4++) {
                float4 v = *(const float4*)(part + (q4 * 32 + eb) * PART_STR + eu * 4);
                pi += v.x; pf += v.y; pg += v.z; po += v.w;
            }

            cc = sigmoidf_(pf) * cc + sigmoidf_(pi) * tanhf(pg);
            hh = sigmoidf_(po) * tanhf(cc);

            int gu = u0 + eu;
            g_h[(ts + 1) & 1][eb * HID + gu] = hh;
            size_t o = ((size_t)ts * BATCH + eb) * HID + gu;
            out[o]           = hh;
            out[OFF_ALL + o] = hh;

            NAMED_BAR(5, 128);                    // all writer threads done
            if (t == 0) {
                __threadfence();
                __stcg(&g_flag[blockIdx.x], ts + 2);   // publish h^{ts+1}
            }
        }
        // warps 4..7 proceed straight to the next wait_flags; it cannot pass
        // until our own flag is set, which orders all intra-CTA reuse.
    }

    if (t < 128) {
        int gu = u0 + eu;
        out[OFF_HT + (size_t)eb * HID + gu] = hh;
        out[OFF_CT + (size_t)eb * HID + gu] = cc;
    }

    // Drain: nobody polls flags anymore after this barrier -> reset for replay.
    end_barrier(lsense);
    if (t == 0) __stcg(&g_flag[blockIdx.x], 0);
}

// ---------------------------------------------------------------------------
extern "C" void kernel_launch(void* const* d_in, const int* in_sizes, int n_in,
                              void* d_out, int out_size) {
    const float* x  = (const float*)d_in[0];   // [T,B,I]
    const float* h0 = (const float*)d_in[1];   // [1,B,H]
    const float* c0 = (const float*)d_in[2];   // [1,B,H]
    const float* Wx = (const float*)d_in[3];   // [4H,I]
    const float* Wh = (const float*)d_in[4];   // [4H,H]
    const float* b  = (const float*)d_in[5];   // [4H]
    float* out = (float*)d_out;

    cudaFuncSetAttribute(lstm_kernel,
                         cudaFuncAttributeMaxDynamicSharedMemorySize, SMEM_BYTES);

    dim3 g1(G4 / 128, (T_STEPS * BATCH) / 64);   // (16, 512)
    pregemm_kernel<<<g1, TPB>>>(x, Wx, b);

    lstm_kernel<<<NCTA, TPB, SMEM_BYTES>>>(Wh, h0, c0, out);
}

// round 4
// speedup vs baseline: 1.6517x; 1.6517x over previous
#include <cuda_runtime.h>
#include <math.h>

// Problem constants (fixed by the reference: T=1024, B=32, I=H=512)
#define T_STEPS 1024
#define BATCH   32
#define HID     512
#define INP     512
#define G4      2048
#define NCTA    128
#define TPB     256

// Output layout: (output[T,B,H], h_T[1,B,H], c_T[1,B,H], all_hidden[T,B,H])
#define OFF_HT  ((size_t)T_STEPS * BATCH * HID)
#define OFF_CT  (OFF_HT + (size_t)BATCH * HID)
#define OFF_ALL (OFF_CT + (size_t)BATCH * HID)

// Precomputed x@Wx^T + b for all timesteps (256 MB, static device mem)
__device__ float g_xp[(size_t)T_STEPS * BATCH * G4];
// Hidden state, double buffered, transposed PAIR layout:
//   g_hp[buf][(k>>1)*64 + b*2 + (k&1)]  -> lane b reads (h[k],h[k+1]) as one b64
__device__ float g_hp[2][256 * 64];
// Grid barrier state (sense-reversing; self-consistent across graph replays)
__device__ unsigned g_count = 0;
__device__ volatile unsigned g_sense = 0;

// ---------------------------------------------------------------------------
// f32x2 helpers
// ---------------------------------------------------------------------------
__device__ __forceinline__ unsigned long long ffma2(
    unsigned long long a, unsigned long long b, unsigned long long c)
{
    unsigned long long d;
    asm("fma.rn.f32x2 %0, %1, %2, %3;" : "=l"(d) : "l"(a), "l"(b), "l"(c));
    return d;
}
__device__ __forceinline__ unsigned long long pack2(float lo, float hi) {
    unsigned long long r;
    asm("mov.b64 %0, {%1, %2};" : "=l"(r) : "f"(lo), "f"(hi));
    return r;
}
__device__ __forceinline__ float hadd2(unsigned long long v) {
    float lo, hi;
    asm("mov.b64 {%0,%1}, %2;" : "=f"(lo), "=f"(hi) : "l"(v));
    return lo + hi;
}
__device__ __forceinline__ void unpack2(unsigned long long v, float& lo, float& hi) {
    asm("mov.b64 {%0,%1}, %2;" : "=f"(lo), "=f"(hi) : "l"(v));
}

// ---------------------------------------------------------------------------
// Phase 1: XP[m][n] = X[m][:].Wx[n][:] + bias[n], M=32768 N=2048 K=512.
// 64x128 tile, 4x8 register block as 4x4 f32x2 pairs, prefetched K-tiles.
// ---------------------------------------------------------------------------
__global__ void __launch_bounds__(256, 2) pregemm_kernel(
    const float* __restrict__ X,
    const float* __restrict__ Wx,
    const float* __restrict__ bias)
{
    __shared__ float As[16][68];
    __shared__ float Bs[16][132];

    const int t  = threadIdx.x;
    const int m0 = blockIdx.y * 64;
    const int n0 = blockIdx.x * 128;
    const int tm = (t >> 4) << 2;
    const int tn = (t & 15) << 3;
    const int lr = t >> 2;
    const int lk = (t & 3) << 2;

    unsigned long long acc[4][4];
#pragma unroll
    for (int i = 0; i < 4; i++)
#pragma unroll
        for (int j = 0; j < 4; j++) acc[i][j] = 0ull;

    const float* Arow  = X  + (size_t)(m0 + lr) * INP + lk;
    const float* Brow0 = Wx + (size_t)(n0 + lr) * INP + lk;
    const float* Brow1 = Wx + (size_t)(n0 + 64 + lr) * INP + lk;

    float4 av = *(const float4*)(Arow);
    float4 b0 = *(const float4*)(Brow0);
    float4 b1 = *(const float4*)(Brow1);

    for (int kt = 0; kt < INP; kt += 16) {
        __syncthreads();
        As[lk + 0][lr] = av.x; As[lk + 1][lr] = av.y;
        As[lk + 2][lr] = av.z; As[lk + 3][lr] = av.w;
        Bs[lk + 0][lr] = b0.x; Bs[lk + 1][lr] = b0.y;
        Bs[lk + 2][lr] = b0.z; Bs[lk + 3][lr] = b0.w;
        Bs[lk + 0][64 + lr] = b1.x; Bs[lk + 1][64 + lr] = b1.y;
        Bs[lk + 2][64 + lr] = b1.z; Bs[lk + 3][64 + lr] = b1.w;
        __syncthreads();

        if (kt + 16 < INP) {
            av = *(const float4*)(Arow  + kt + 16);
            b0 = *(const float4*)(Brow0 + kt + 16);
            b1 = *(const float4*)(Brow1 + kt + 16);
        }

#pragma unroll
        for (int k = 0; k < 16; k++) {
            float4 a = *(const float4*)&As[k][tm];
            ulonglong2 p = *(const ulonglong2*)&Bs[k][tn];      // pairs n+0..3
            ulonglong2 q = *(const ulonglong2*)&Bs[k][tn + 4];  // pairs n+4..7
            float ar[4] = {a.x, a.y, a.z, a.w};
#pragma unroll
            for (int i = 0; i < 4; i++) {
                unsigned long long aa = pack2(ar[i], ar[i]);
                acc[i][0] = ffma2(aa, p.x, acc[i][0]);
                acc[i][1] = ffma2(aa, p.y, acc[i][1]);
                acc[i][2] = ffma2(aa, q.x, acc[i][2]);
                acc[i][3] = ffma2(aa, q.y, acc[i][3]);
            }
        }
    }

    float bl[8];
#pragma unroll
    for (int j = 0; j < 8; j++) bl[j] = bias[n0 + tn + j];
#pragma unroll
    for (int i = 0; i < 4; i++) {
        float r[8];
#pragma unroll
        for (int j = 0; j < 4; j++) unpack2(acc[i][j], r[2*j], r[2*j+1]);
        float4 s0 = make_float4(r[0] + bl[0], r[1] + bl[1], r[2] + bl[2], r[3] + bl[3]);
        float4 s1 = make_float4(r[4] + bl[4], r[5] + bl[5], r[6] + bl[6], r[7] + bl[7]);
        float* dst = g_xp + (size_t)(m0 + tm + i) * G4 + n0 + tn;
        *(float4*)dst       = s0;
        *(float4*)(dst + 4) = s1;
    }
}

// ---------------------------------------------------------------------------
// Phase 2 helpers
// ---------------------------------------------------------------------------
__device__ __forceinline__ float sigmoidf_(float x) {
    return 1.f / (1.f + expf(-x));
}

__device__ __forceinline__ void grid_barrier(unsigned& lsense) {
    __syncthreads();
    if (threadIdx.x == 0) {
        __threadfence();
        unsigned s = lsense ^ 1u;
        lsense = s;
        if (atomicAdd(&g_count, 1u) == (unsigned)(gridDim.x - 1)) {
            atomicExch(&g_count, 0u);
            __threadfence();
            g_sense = s;
        } else {
            while (g_sense != s) __nanosleep(32);
        }
        __threadfence();
    }
    __syncthreads();
}

// SMEM (floats): ws[16 cols][512 k] | part[256 rows][20]
#define PART_STR  20
#define SM_WS     0
#define SM_PART   (16 * 512)
#define SM_TOTALF (SM_PART + 256 * PART_STR)     // 13312 floats
#define SMEM_BYTES (SM_TOTALF * 4)               // 53248 B

// ---------------------------------------------------------------------------
// Phase 2: 128 persistent CTAs x 256 thr. CTA owns 4 hidden units (16 gate
// cols, SMEM-resident). Warp w = k-eighth, covers ALL 16 cols; lane = batch.
// h loaded coalesced straight to registers (transposed pair layout, ld.cg),
// dot products in fma.rn.f32x2, partial reduce via SMEM, atomic grid barrier.
// ---------------------------------------------------------------------------
__global__ void __launch_bounds__(256, 1) lstm_kernel(
    const float* __restrict__ Wh,
    const float* __restrict__ h0,
    const float* __restrict__ c0,
    float* __restrict__ out)
{
    extern __shared__ __align__(16) float sm[];
    float* ws   = sm + SM_WS;
    float* part = sm + SM_PART;

    const int t    = threadIdx.x;
    const int lane = t & 31;
    const int w8   = t >> 5;            // k-eighth 0..7
    const int u0   = blockIdx.x * 4;

    unsigned lsense = g_sense;

    // Wh columns -> SMEM: ws[col][k], col = unit*4 + gate (i,f,g,o)
#pragma unroll
    for (int i = 0; i < 8; i++) {
        int j  = t + i * 256;
        int lc = j >> 7;
        int kf = j & 127;
        int ul = lc >> 2, q = lc & 3;
        float4 v = *(const float4*)(Wh + (size_t)(q * HID + u0 + ul) * HID + kf * 4);
        *(float4*)(ws + lc * 512 + kf * 4) = v;
    }

    const int eb = t >> 2;              // batch   (t < 128)
    const int eu = t & 3;               // local unit
    float cc = 0.f, hh = 0.f;
    if (t < 128) {
        int u = u0 + eu;
        cc = c0[eb * HID + u];
        hh = h0[eb * HID + u];
        g_hp[0][(u >> 1) * 64 + eb * 2 + (u & 1)] = hh;
    }

    grid_barrier(lsense);               // h^0 visible everywhere

    const float* wbase = ws + w8 * 64;  // this warp's k-window within each col

    for (int ts = 0; ts < T_STEPS; ts++) {
        // xp prefetch (independent of h; overlaps the h load + compute)
        float xq0 = 0.f, xq1 = 0.f, xq2 = 0.f, xq3 = 0.f;
        if (t < 128) {
            const float* xp = g_xp + ((size_t)ts * BATCH + eb) * G4 + (u0 + eu);
            xq0 = __ldg(xp);
            xq1 = __ldg(xp + 512);
            xq2 = __ldg(xp + 1024);
            xq3 = __ldg(xp + 1536);
        }

        // Load my k-eighth of h for my batch lane: 32 coalesced b64 loads
        unsigned long long h2[32];
        const unsigned long long* hb = (const unsigned long long*)
            (g_hp[ts & 1] + (w8 * 32) * 64 + lane * 2);
#pragma unroll
        for (int kk = 0; kk < 32; kk++)
            h2[kk] = __ldcg(hb + kk * 32);          // stride 64 floats = 32 ull

        // 16 gate-col partial dots over 64 k-values, 4 cols at a time
        float* prow = part + (w8 * 32 + lane) * PART_STR;
#pragma unroll
        for (int jb = 0; jb < 4; jb++) {
            unsigned long long a0 = 0ull, a1 = 0ull, a2 = 0ull, a3 = 0ull;
            const float* wj = wbase + (jb * 4) * 512;
#pragma unroll 8
            for (int k4 = 0; k4 < 16; k4++) {
                ulonglong2 hv;
                hv.x = h2[k4 * 2];
                hv.y = h2[k4 * 2 + 1];
                ulonglong2 w0 = *(const ulonglong2*)(wj + 0 * 512 + k4 * 4);
                ulonglong2 w1 = *(const ulonglong2*)(wj + 1 * 512 + k4 * 4);
                ulonglong2 w2 = *(const ulonglong2*)(wj + 2 * 512 + k4 * 4);
                ulonglong2 w3 = *(const ulonglong2*)(wj + 3 * 512 + k4 * 4);
                a0 = ffma2(hv.x, w0.x, a0); a0 = ffma2(hv.y, w0.y, a0);
                a1 = ffma2(hv.x, w1.x, a1); a1 = ffma2(hv.y, w1.y, a1);
                a2 = ffma2(hv.x, w2.x, a2); a2 = ffma2(hv.y, w2.y, a2);
                a3 = ffma2(hv.x, w3.x, a3); a3 = ffma2(hv.y, w3.y, a3);
            }
            *(float4*)(prow + jb * 4) =
                make_float4(hadd2(a0), hadd2(a1), hadd2(a2), hadd2(a3));
        }
        __syncthreads();                             // partials visible

        if (t < 128) {
            float pi = xq0, pf = xq1, pg = xq2, po = xq3;
#pragma unroll
            for (int w = 0; w < 8; w++) {
                float4 v = *(const float4*)(part + (w * 32 + eb) * PART_STR + eu * 4);
                pi += v.x; pf += v.y; pg += v.z; po += v.w;
            }

            cc = sigmoidf_(pf) * cc + sigmoidf_(pi) * tanhf(pg);
            hh = sigmoidf_(po) * tanhf(cc);

            int u = u0 + eu;
            g_hp[(ts + 1) & 1][(u >> 1) * 64 + eb * 2 + (u & 1)] = hh;  // publish first
            size_t o = ((size_t)ts * BATCH + eb) * HID + u;
            out[o]           = hh;
            out[OFF_ALL + o] = hh;
        }

        grid_barrier(lsense);
    }

    if (t < 128) {
        int u = u0 + eu;
        out[OFF_HT + (size_t)eb * HID + u] = hh;
        out[OFF_CT + (size_t)eb * HID + u] = cc;
    }
}

// ---------------------------------------------------------------------------
extern "C" void kernel_launch(void* const* d_in, const int* in_sizes, int n_in,
                              void* d_out, int out_size) {
    const float* x  = (const float*)d_in[0];   // [T,B,I]
    const float* h0 = (const float*)d_in[1];   // [1,B,H]
    const float* c0 = (const float*)d_in[2];   // [1,B,H]
    const float* Wx = (const float*)d_in[3];   // [4H,I]
    const float* Wh = (const float*)d_in[4];   // [4H,H]
    const float* b  = (const float*)d_in[5];   // [4H]
    float* out = (float*)d_out;

    cudaFuncSetAttribute(lstm_kernel,
                         cudaFuncAttributeMaxDynamicSharedMemorySize, SMEM_BYTES);

    dim3 g1(G4 / 128, (T_STEPS * BATCH) / 64);   // (16, 512)
    pregemm_kernel<<<g1, TPB>>>(x, Wx, b);

    lstm_kernel<<<NCTA, TPB, SMEM_BYTES>>>(Wh, h0, c0, out);
}